// round 5
// baseline (speedup 1.0000x reference)
#include <cuda_runtime.h>

#define BB 16
#define CC_FEAT 96
#define HH 128
#define WW 128
#define HWSZ (HH*WW)

typedef unsigned long long u64;

__device__ __forceinline__ u64 ffma2(u64 a, u64 b, u64 c) {
    u64 d;
    asm("fma.rn.f32x2 %0, %1, %2, %3;" : "=l"(d) : "l"(a), "l"(b), "l"(c));
    return d;
}
__device__ __forceinline__ u64 pack2(float lo, float hi) {
    u64 d; asm("mov.b64 %0, {%1, %2};" : "=l"(d) : "f"(lo), "f"(hi)); return d;
}
__device__ __forceinline__ void unpack2(u64 v, float& lo, float& hi) {
    asm("mov.b64 {%0, %1}, %2;" : "=f"(lo), "=f"(hi) : "l"(v));
}

// ---- scratch (device globals; no allocation allowed) ----
__device__ float g_flow [BB*2  *HWSZ];
__device__ float g_feat2[BB*CC_FEAT*HWSZ];
__device__ float g_corr [BB*49 *HWSZ];
__device__ float g_x1   [BB*128*HWSZ];
__device__ float g_x2   [BB*64 *HWSZ];
__device__ float g_x3   [BB*32 *HWSZ];

// ---------------------------------------------------------------------------
// 1) upflow: depthwise transposed conv, stride 2, 4x4 (flipped), pad 2
// ---------------------------------------------------------------------------
__global__ void k_upflow(const float* __restrict__ tf, const float* __restrict__ wu) {
    int idx = blockIdx.x * blockDim.x + threadIdx.x;      // 512*1024 = 524288 exact
    int ox = idx & 127, oy = (idx >> 7) & 127, c = (idx >> 14) & 1, b = idx >> 15;
    float acc = 0.f;
#pragma unroll
    for (int ky = 0; ky < 4; ky++) {
        int iy = oy + ky - 2;
        if (iy < 0 || iy > 126 || (iy & 1)) continue;
        iy >>= 1;
#pragma unroll
        for (int kx = 0; kx < 4; kx++) {
            int ix = ox + kx - 2;
            if (ix < 0 || ix > 126 || (ix & 1)) continue;
            ix >>= 1;
            acc += wu[c*16 + (3-ky)*4 + (3-kx)] * tf[((b*2 + c)*64 + iy)*64 + ix];
        }
    }
    g_flow[idx] = acc;
}

// ---------------------------------------------------------------------------
// 2) backward warp of featuresSecond by flow*2.5 (bilinear, zero pad, mask)
// ---------------------------------------------------------------------------
__global__ void k_warp(const float* __restrict__ feat) {
    int x = threadIdx.x;        // 128
    int y = blockIdx.x;         // 128
    int b = blockIdx.y;         // 16
    int base = b*2*HWSZ + y*WW + x;
    float fx = (float)x + 2.5f * g_flow[base];
    float fy = (float)y + 2.5f * g_flow[base + HWSZ];
    float x0f = floorf(fx), y0f = floorf(fy);
    float wx1 = fx - x0f, wx0 = 1.f - wx1;
    float wy1 = fy - y0f, wy0 = 1.f - wy1;
    int x0 = (int)x0f, y0 = (int)y0f;
    int x1 = x0 + 1,  y1 = y0 + 1;
    bool vx0 = (x0 >= 0) & (x0 < WW), vx1 = (x1 >= 0) & (x1 < WW);
    bool vy0 = (y0 >= 0) & (y0 < HH), vy1 = (y1 >= 0) & (y1 < HH);
    float wa = wx0*wy0, wb = wx1*wy0, wc = wx0*wy1, wd = wx1*wy1;
    float m = wa*(float)(vx0&&vy0) + wb*(float)(vx1&&vy0)
            + wc*(float)(vx0&&vy1) + wd*(float)(vx1&&vy1);
    float mask = (m > 0.999f) ? 1.f : 0.f;
    float ea = (vx0&&vy0) ? wa*mask : 0.f;
    float eb = (vx1&&vy0) ? wb*mask : 0.f;
    float ec = (vx0&&vy1) ? wc*mask : 0.f;
    float ed = (vx1&&vy1) ? wd*mask : 0.f;
    int xa = min(max(x0,0),WW-1), xb = min(max(x1,0),WW-1);
    int ya = min(max(y0,0),HH-1), yb = min(max(y1,0),HH-1);
    const float* fp = feat + (size_t)b*CC_FEAT*HWSZ;
    int oa = ya*WW+xa, ob = ya*WW+xb, oc = yb*WW+xa, od = yb*WW+xb;
    float* outp = g_feat2 + (size_t)b*CC_FEAT*HWSZ + y*WW + x;
#pragma unroll 4
    for (int c = 0; c < CC_FEAT; c++) {
        float v = ea*fp[oa] + eb*fp[ob] + ec*fp[oc] + ed*fp[od];
        *outp = v;
        fp += HWSZ; outp += HWSZ;
    }
}

// ---------------------------------------------------------------------------
// 3) correlation (7x7, mean over 96 ch) + leaky relu -> g_corr (B,49,H,W)
// ---------------------------------------------------------------------------
__global__ void k_corr(const float* __restrict__ first) {
    const int tx = threadIdx.x, ty = threadIdx.y;
    const int x0 = blockIdx.x*32, y0 = blockIdx.y*8, b = blockIdx.z;
    __shared__ float s_f[4][8][32];
    __shared__ float s_p[4][14][40];   // 38 used, padded
    float acc[49];
#pragma unroll
    for (int i = 0; i < 49; i++) acc[i] = 0.f;
    const int tid = ty*32 + tx;

    for (int c0 = 0; c0 < CC_FEAT; c0 += 4) {
#pragma unroll
        for (int cc = 0; cc < 4; cc++)
            s_f[cc][ty][tx] = first[((b*CC_FEAT + c0+cc)*HH + y0+ty)*WW + x0+tx];
        for (int i = tid; i < 4*14*38; i += 256) {
            int cc  = i / (14*38);
            int r   = (i / 38) % 14;
            int col = i % 38;
            int gy = y0 + r - 3, gx = x0 + col - 3;
            float v = 0.f;
            if (gy >= 0 && gy < HH && gx >= 0 && gx < WW)
                v = g_feat2[((b*CC_FEAT + c0+cc)*HH + gy)*WW + gx];
            s_p[cc][r][col] = v;
        }
        __syncthreads();
#pragma unroll
        for (int cc = 0; cc < 4; cc++) {
            float f = s_f[cc][ty][tx];
#pragma unroll
            for (int dy = 0; dy < 7; dy++)
#pragma unroll
                for (int dx = 0; dx < 7; dx++)
                    acc[dy*7+dx] += f * s_p[cc][ty+dy][tx+dx];
        }
        __syncthreads();
    }
    const float inv = 1.f/96.f;
#pragma unroll
    for (int d = 0; d < 49; d++) {
        float v = acc[d]*inv;
        v = (v >= 0.f) ? v : 0.1f*v;
        g_corr[((b*49 + d)*HH + y0+ty)*WW + x0+tx] = v;
    }
}

// ---------------------------------------------------------------------------
// 4) 3x3 conv via packed f32x2 math.
//    block (16,16); spatial tile 32(w) x 64(h); thread: 2x-pair x 4y x 8co.
// ---------------------------------------------------------------------------
template<int CIN, int COUT, bool RELU>
__device__ __forceinline__ void conv3_f32x2_body(const float* __restrict__ in,
                                                 const float* __restrict__ wt,
                                                 const float* __restrict__ bias,
                                                 float* __restrict__ out) {
    const int tx = threadIdx.x, ty = threadIdx.y;
    const int tid = ty*16 + tx;
    const int warp = tid >> 5, lane = tid & 31;
    const int x0 = blockIdx.x*32, y0 = blockIdx.y*64;
    const int ng = COUT/8;
    const int b  = blockIdx.z / ng;
    const int co0 = (blockIdx.z % ng)*8;

    // s_in2[ci][r][jp]: float2, r: gy = y0+r-1 (66 rows), jp: gx pair = x0 + 2*jp - 2
    __shared__ float2 s_in2[4][66][18];
    __shared__ float2 s_w[4][9][8];     // duplicated {w,w}

    u64 acc[4][8];
#pragma unroll
    for (int p = 0; p < 4; p++)
#pragma unroll
        for (int co = 0; co < 8; co++) acc[p][co] = 0ULL;

    for (int c0 = 0; c0 < CIN; c0 += 4) {
        // ---- weights: 4*9*8 = 288 float2 ----
        for (int i = tid; i < 288; i += 256) {
            int ci = i/72, r = i%72, k = r/8, co = r%8;
            float v = (c0+ci < CIN) ? wt[((co0+co)*CIN + c0+ci)*9 + k] : 0.f;
            s_w[ci][k][co] = make_float2(v, v);
        }
        // ---- input tile: 4 x 66 rows x 36 floats ----
#pragma unroll
        for (int ci = 0; ci < 4; ci++) {
            const bool cval = (c0 + ci < CIN);
            const float* src = in + ((size_t)(b*CIN + c0 + ci))*HWSZ;
            for (int r = warp; r < 66; r += 8) {
                int gy = y0 + r - 1;
                float* dst = (float*)&s_in2[ci][r][0];
                bool rowok = cval && (gy >= 0) && (gy < HH);
                int gx = x0 + lane - 2;
                float v = 0.f;
                if (rowok && gx >= 0 && gx < WW) v = src[gy*WW + gx];
                dst[lane] = v;
                if (lane < 4) {
                    int gx2 = x0 + lane + 30;
                    float v2 = 0.f;
                    if (rowok && gx2 >= 0 && gx2 < WW) v2 = src[gy*WW + gx2];
                    dst[lane + 32] = v2;
                }
            }
        }
        __syncthreads();

#pragma unroll
        for (int ci = 0; ci < 4; ci++) {
#pragma unroll
            for (int ky = 0; ky < 3; ky++) {
                u64 pr[4][3];
#pragma unroll
                for (int py = 0; py < 4; py++) {
                    int r = ty + 16*py + ky;
                    const float2* rowp = &s_in2[ci][r][0];
                    float2 P0 = rowp[tx];
                    float2 P1 = rowp[tx + 1];
                    float2 P2 = rowp[tx + 2];
                    pr[py][0] = pack2(P0.y, P1.x);
                    pr[py][1] = pack2(P1.x, P1.y);
                    pr[py][2] = pack2(P1.y, P2.x);
                }
#pragma unroll
                for (int kx = 0; kx < 3; kx++) {
                    u64 wv[8];
#pragma unroll
                    for (int co = 0; co < 8; co++)
                        wv[co] = *(const u64*)&s_w[ci][ky*3 + kx][co];
#pragma unroll
                    for (int py = 0; py < 4; py++)
#pragma unroll
                        for (int co = 0; co < 8; co++)
                            acc[py][co] = ffma2(pr[py][kx], wv[co], acc[py][co]);
                }
            }
        }
        __syncthreads();
    }

#pragma unroll
    for (int py = 0; py < 4; py++) {
        int gy = y0 + ty + 16*py;
#pragma unroll
        for (int co = 0; co < 8; co++) {
            float lo, hi; unpack2(acc[py][co], lo, hi);
            float bs = bias[co0 + co];
            lo += bs; hi += bs;
            if (RELU) {
                lo = (lo >= 0.f) ? lo : 0.1f*lo;
                hi = (hi >= 0.f) ? hi : 0.1f*hi;
            }
            *(float2*)&out[((b*COUT + co0+co)*HH + gy)*WW + x0 + 2*tx] = make_float2(lo, hi);
        }
    }
}

__global__ void __launch_bounds__(256, 2)
k_conv1(const float* __restrict__ wt, const float* __restrict__ bias) {
    conv3_f32x2_body<49, 128, true>(g_corr, wt, bias, g_x1);
}
__global__ void __launch_bounds__(256, 2)
k_conv2(const float* __restrict__ wt, const float* __restrict__ bias) {
    conv3_f32x2_body<128, 64, true>(g_x1, wt, bias, g_x2);
}
__global__ void __launch_bounds__(256, 2)
k_conv3k(const float* __restrict__ wt, const float* __restrict__ bias) {
    conv3_f32x2_body<64, 32, true>(g_x2, wt, bias, g_x3);
}

// ---------------------------------------------------------------------------
// 5) final 5x5 conv (32->2, pad 2) + bias + flow residual -> d_out
// ---------------------------------------------------------------------------
__global__ void k_conv4(const float* __restrict__ wt, const float* __restrict__ bias,
                        float* __restrict__ out) {
    const int tx = threadIdx.x, ty = threadIdx.y;
    const int x0 = blockIdx.x*32, y0 = blockIdx.y*32;
    const int b = blockIdx.z;
    __shared__ float s_in[4][36][36];
    __shared__ float s_w[2][4][25];
    float acc[4][2];
#pragma unroll
    for (int p = 0; p < 4; p++) { acc[p][0] = 0.f; acc[p][1] = 0.f; }
    const int tid = ty*32 + tx;

    for (int c0 = 0; c0 < 32; c0 += 4) {
        if (tid < 200) {
            int co = tid/100, r = tid%100, ci = r/25, k = r%25;
            s_w[co][ci][k] = wt[(co*32 + c0+ci)*25 + k];
        }
        for (int i = tid; i < 4*36*36; i += 256) {
            int cc = i/(36*36), r = (i/36)%36, col = i%36;
            int gy = y0 + r - 2, gx = x0 + col - 2;
            float v = 0.f;
            if (gy >= 0 && gy < HH && gx >= 0 && gx < WW)
                v = g_x3[((b*32 + c0+cc)*HH + gy)*WW + gx];
            s_in[cc][r][col] = v;
        }
        __syncthreads();
        for (int ci = 0; ci < 4; ci++) {
#pragma unroll
            for (int k = 0; k < 25; k++) {
                const int ky = k/5, kx = k%5;
                float w0 = s_w[0][ci][k];
                float w1 = s_w[1][ci][k];
#pragma unroll
                for (int p = 0; p < 4; p++) {
                    float iv = s_in[ci][ty + 8*p + ky][tx + kx];
                    acc[p][0] += iv * w0;
                    acc[p][1] += iv * w1;
                }
            }
        }
        __syncthreads();
    }
#pragma unroll
    for (int co = 0; co < 2; co++) {
        float bs = bias[co];
#pragma unroll
        for (int p = 0; p < 4; p++) {
            int o = ((b*2 + co)*HH + y0 + ty + 8*p)*WW + x0 + tx;
            out[o] = g_flow[o] + bs + acc[p][co];
        }
    }
}

// ---------------------------------------------------------------------------
extern "C" void kernel_launch(void* const* d_in, const int* in_sizes, int n_in,
                              void* d_out, int out_size) {
    const float* featFirst  = (const float*)d_in[2];
    const float* featSecond = (const float*)d_in[3];
    const float* tflow      = (const float*)d_in[4];
    const float* wu         = (const float*)d_in[5];
    const float* w1 = (const float*)d_in[6];
    const float* b1 = (const float*)d_in[7];
    const float* w2 = (const float*)d_in[8];
    const float* b2 = (const float*)d_in[9];
    const float* w3 = (const float*)d_in[10];
    const float* b3 = (const float*)d_in[11];
    const float* w4 = (const float*)d_in[12];
    const float* b4 = (const float*)d_in[13];
    float* out = (float*)d_out;

    k_upflow<<<512, 1024>>>(tflow, wu);
    k_warp<<<dim3(128, 16), 128>>>(featSecond);
    k_corr<<<dim3(4, 16, 16), dim3(32, 8)>>>(featFirst);
    k_conv1 <<<dim3(4, 2, 16*16), dim3(16, 16)>>>(w1, b1);
    k_conv2 <<<dim3(4, 2, 16*8),  dim3(16, 16)>>>(w2, b2);
    k_conv3k<<<dim3(4, 2, 16*4),  dim3(16, 16)>>>(w3, b3);
    k_conv4 <<<dim3(4, 4, 16), dim3(32, 8)>>>(w4, b4, out);
}

// round 6
// speedup vs baseline: 2.6990x; 2.6990x over previous
#include <cuda_runtime.h>
#include <cuda_bf16.h>

#define BB 16
#define CC_FEAT 96
#define HH 128
#define WW 128
#define HWSZ (HH*WW)

typedef unsigned int u32;

// ---- scratch (device globals; no allocation allowed) ----
__device__ float g_flow [BB*2  *HWSZ];
__device__ float g_feat2[BB*CC_FEAT*HWSZ];
__device__ float g_corr [BB*49 *HWSZ];
__device__ float g_x1   [BB*128*HWSZ];
__device__ float g_x2   [BB*64 *HWSZ];
__device__ float g_x3   [BB*32 *HWSZ];

// split bf16 weights, transposed to [9][COUT][CIN_PAD]
__device__ __nv_bfloat16 g_w1h[9*128*64], g_w1l[9*128*64];
__device__ __nv_bfloat16 g_w2h[9*64*128], g_w2l[9*64*128];
__device__ __nv_bfloat16 g_w3h[9*32*64],  g_w3l[9*32*64];

__device__ __forceinline__ void split_bf16(float x, unsigned short& h, unsigned short& l) {
    __nv_bfloat16 bh = __float2bfloat16(x);
    float r = x - __bfloat162float(bh);
    __nv_bfloat16 bl = __float2bfloat16(r);
    h = __bfloat16_as_ushort(bh);
    l = __bfloat16_as_ushort(bl);
}

__device__ __forceinline__ void mma_bf16(float* c, const u32* a, const u32* b) {
    asm volatile("mma.sync.aligned.m16n8k16.row.col.f32.bf16.bf16.f32 "
        "{%0,%1,%2,%3}, {%4,%5,%6,%7}, {%8,%9}, {%0,%1,%2,%3};"
        : "+f"(c[0]), "+f"(c[1]), "+f"(c[2]), "+f"(c[3])
        : "r"(a[0]), "r"(a[1]), "r"(a[2]), "r"(a[3]), "r"(b[0]), "r"(b[1]));
}

// ---------------------------------------------------------------------------
// weight prep: w[COUT][CIN][3][3] fp32 -> [9][COUT][CIN_PAD] bf16 hi/lo
// ---------------------------------------------------------------------------
__global__ void k_wprep(const float* __restrict__ w, __nv_bfloat16* __restrict__ oh,
                        __nv_bfloat16* __restrict__ ol, int COUT, int CIN, int CIN_PAD) {
    int idx = blockIdx.x*256 + threadIdx.x;
    int tot = 9*COUT*CIN_PAD;
    if (idx >= tot) return;
    int s9 = idx / (COUT*CIN_PAD);
    int r  = idx % (COUT*CIN_PAD);
    int co = r / CIN_PAD, ci = r % CIN_PAD;
    float v = (ci < CIN) ? w[(co*CIN + ci)*9 + s9] : 0.f;
    unsigned short h, l;
    split_bf16(v, h, l);
    oh[idx] = __ushort_as_bfloat16(h);
    ol[idx] = __ushort_as_bfloat16(l);
}

// ---------------------------------------------------------------------------
// MMA conv: 3x3 pad1 conv as 9 shifted GEMMs, bf16 hi/lo split (3 mma/term).
// One block = one output row y, one batch, all COUT x 128 pixels.
// smem B: [NCHUNK][3 rows][132 cols][16 k] bf16 (hi & lo), staged once.
// smem A: [2 buf][2 split][COUT][16] double-buffered per (chunk,shift).
// ---------------------------------------------------------------------------
template<int COUT, int CIN, int NCHUNK, int WGM, int WGN, int WM, int WN, int NA>
__device__ __forceinline__ void convmma_body(
        const __nv_bfloat16* __restrict__ wh, const __nv_bfloat16* __restrict__ wl,
        const float* __restrict__ in, const float* __restrict__ bias,
        float* __restrict__ out) {
    const int tid = threadIdx.x;
    const int lane = tid & 31, warp = tid >> 5;
    const int wm = warp % WGM, wn = warp / WGM;
    const int y = blockIdx.x, b = blockIdx.y;
    const int m_base = wm * (WM*16);
    const int n_base = wn * (WN*8);
    const int gid = lane >> 2;            // groupID
    const int k0  = (lane & 3) * 2;       // k pair base

    extern __shared__ char smraw[];
    __nv_bfloat16* s_bh = (__nv_bfloat16*)smraw;
    __nv_bfloat16* s_bl = s_bh + NCHUNK*3*132*16;
    __nv_bfloat16* s_a  = s_bl + NCHUNK*3*132*16;   // [2][2][COUT][16]

    float acc[WM][WN][4];
#pragma unroll
    for (int mi = 0; mi < WM; mi++)
#pragma unroll
        for (int fi = 0; fi < WN; fi++)
#pragma unroll
            for (int q = 0; q < 4; q++) acc[mi][fi][q] = 0.f;

    // ---- stage B: all CIN_PAD channels, 3 rows (y-1..y+1), 130 cols ----
    {
        const int PAIRS = NCHUNK*8;   // CIN_PAD/2
        const float* basep = in + (size_t)b*CIN*HWSZ;
        for (int i = tid; i < 130*PAIRS*3; i += 256) {
            int col = i % 130;
            int t2  = i / 130;
            int pr  = t2 % PAIRS;
            int row = t2 / PAIRS;
            int gx = col - 1, gy = y + row - 1;
            int ci0 = pr*2;
            float v0 = 0.f, v1 = 0.f;
            if (gy >= 0 && gy < HH && gx >= 0 && gx < WW) {
                const float* p = basep + gy*WW + gx;
                if (ci0     < CIN) v0 = p[(size_t)ci0    *HWSZ];
                if (ci0 + 1 < CIN) v1 = p[(size_t)(ci0+1)*HWSZ];
            }
            unsigned short h0, l0, h1, l1;
            split_bf16(v0, h0, l0);
            split_bf16(v1, h1, l1);
            int sidx = (((pr >> 3)*3 + row)*132 + col)*16 + (pr & 7)*2;
            *(u32*)&s_bh[sidx] = ((u32)h1 << 16) | h0;
            *(u32*)&s_bl[sidx] = ((u32)l1 << 16) | l0;
        }
    }

    // ---- main loop: chunk-major, 9 shifts inner; A double-buffered ----
    const u32* whp = (const u32*)wh;
    const u32* wlp = (const u32*)wl;
    const int CPAD2 = NCHUNK*8;   // CIN_PAD/2 (u32 stride per cout row)
    u32 pf[NA];

    // prefetch it=0 (chunk 0, shift 0)
#pragma unroll
    for (int t = 0; t < NA; t++) {
        int j = tid + t*256;
        int s = j / (COUT*8); int j2 = j % (COUT*8);
        int co = j2 >> 3, kp = j2 & 7;
        const u32* src = s ? wlp : whp;
        pf[t] = src[(0*COUT + co)*CPAD2 + 0*8 + kp];
    }

    const int NIT = NCHUNK*9;
    for (int it = 0; it < NIT; it++) {
        const int buf = it & 1;
        const int chunk = it / 9, s9 = it % 9;
        const int ky = s9 / 3, kx = s9 % 3;

        // store prefetched A
#pragma unroll
        for (int t = 0; t < NA; t++) {
            int j = tid + t*256;
            int s = j / (COUT*8); int j2 = j % (COUT*8);
            int co = j2 >> 3, kp = j2 & 7;
            *(u32*)&s_a[((buf*2 + s)*COUT + co)*16 + kp*2] = pf[t];
        }
        // prefetch next
        if (it + 1 < NIT) {
            int nc = (it+1) / 9, ns = (it+1) % 9;
#pragma unroll
            for (int t = 0; t < NA; t++) {
                int j = tid + t*256;
                int s = j / (COUT*8); int j2 = j % (COUT*8);
                int co = j2 >> 3, kp = j2 & 7;
                const u32* src = s ? wlp : whp;
                pf[t] = src[(ns*COUT + co)*CPAD2 + nc*8 + kp];
            }
        }
        __syncthreads();

        // A fragments (hi & lo)
        u32 a_h[WM][4], a_l[WM][4];
#pragma unroll
        for (int mi = 0; mi < WM; mi++) {
            int r0 = m_base + mi*16 + gid;
            const __nv_bfloat16* ah = &s_a[((buf*2 + 0)*COUT)*16];
            const __nv_bfloat16* al = &s_a[((buf*2 + 1)*COUT)*16];
            a_h[mi][0] = *(const u32*)&ah[(r0    )*16 + k0    ];
            a_h[mi][1] = *(const u32*)&ah[(r0 + 8)*16 + k0    ];
            a_h[mi][2] = *(const u32*)&ah[(r0    )*16 + k0 + 8];
            a_h[mi][3] = *(const u32*)&ah[(r0 + 8)*16 + k0 + 8];
            a_l[mi][0] = *(const u32*)&al[(r0    )*16 + k0    ];
            a_l[mi][1] = *(const u32*)&al[(r0 + 8)*16 + k0    ];
            a_l[mi][2] = *(const u32*)&al[(r0    )*16 + k0 + 8];
            a_l[mi][3] = *(const u32*)&al[(r0 + 8)*16 + k0 + 8];
        }

        // B fragments per n-tile; 3 split-combos of mma
        const __nv_bfloat16* bh_row = s_bh + ((chunk*3 + ky)*132)*16;
        const __nv_bfloat16* bl_row = s_bl + ((chunk*3 + ky)*132)*16;
#pragma unroll
        for (int fi = 0; fi < WN; fi++) {
            int coln = n_base + fi*8 + gid + kx;
            u32 b_h[2], b_l[2];
            b_h[0] = *(const u32*)&bh_row[coln*16 + k0    ];
            b_h[1] = *(const u32*)&bh_row[coln*16 + k0 + 8];
            b_l[0] = *(const u32*)&bl_row[coln*16 + k0    ];
            b_l[1] = *(const u32*)&bl_row[coln*16 + k0 + 8];
#pragma unroll
            for (int mi = 0; mi < WM; mi++) {
                mma_bf16(acc[mi][fi], a_h[mi], b_h);
                mma_bf16(acc[mi][fi], a_l[mi], b_h);
                mma_bf16(acc[mi][fi], a_h[mi], b_l);
            }
        }
    }

    // ---- epilogue: bias + leaky relu + store fp32 ----
#pragma unroll
    for (int mi = 0; mi < WM; mi++) {
        int r0 = m_base + mi*16 + gid;
        float bi0 = bias[r0], bi1 = bias[r0 + 8];
#pragma unroll
        for (int fi = 0; fi < WN; fi++) {
            int n = n_base + fi*8 + (lane & 3)*2;
            float d0 = acc[mi][fi][0] + bi0;
            float d1 = acc[mi][fi][1] + bi0;
            float d2 = acc[mi][fi][2] + bi1;
            float d3 = acc[mi][fi][3] + bi1;
            d0 = (d0 >= 0.f) ? d0 : 0.1f*d0;
            d1 = (d1 >= 0.f) ? d1 : 0.1f*d1;
            d2 = (d2 >= 0.f) ? d2 : 0.1f*d2;
            d3 = (d3 >= 0.f) ? d3 : 0.1f*d3;
            *(float2*)&out[((size_t)(b*COUT + r0    )*HH + y)*WW + n] = make_float2(d0, d1);
            *(float2*)&out[((size_t)(b*COUT + r0 + 8)*HH + y)*WW + n] = make_float2(d2, d3);
        }
    }
}

__global__ void __launch_bounds__(256, 1)
k_conv1m(const float* __restrict__ bias) {
    convmma_body<128, 49, 4, 4, 2, 2, 8, 8>(g_w1h, g_w1l, g_corr, bias, g_x1);
}
__global__ void __launch_bounds__(256, 1)
k_conv2m(const float* __restrict__ bias) {
    convmma_body<64, 128, 8, 2, 4, 2, 4, 4>(g_w2h, g_w2l, g_x1, bias, g_x2);
}
__global__ void __launch_bounds__(256, 1)
k_conv3m(const float* __restrict__ bias) {
    convmma_body<32, 64, 4, 2, 4, 1, 4, 2>(g_w3h, g_w3l, g_x2, bias, g_x3);
}

// ---------------------------------------------------------------------------
// upflow
// ---------------------------------------------------------------------------
__global__ void k_upflow(const float* __restrict__ tf, const float* __restrict__ wu) {
    int idx = blockIdx.x * blockDim.x + threadIdx.x;
    int ox = idx & 127, oy = (idx >> 7) & 127, c = (idx >> 14) & 1, b = idx >> 15;
    float acc = 0.f;
#pragma unroll
    for (int ky = 0; ky < 4; ky++) {
        int iy = oy + ky - 2;
        if (iy < 0 || iy > 126 || (iy & 1)) continue;
        iy >>= 1;
#pragma unroll
        for (int kx = 0; kx < 4; kx++) {
            int ix = ox + kx - 2;
            if (ix < 0 || ix > 126 || (ix & 1)) continue;
            ix >>= 1;
            acc += wu[c*16 + (3-ky)*4 + (3-kx)] * tf[((b*2 + c)*64 + iy)*64 + ix];
        }
    }
    g_flow[idx] = acc;
}

// ---------------------------------------------------------------------------
// backward warp
// ---------------------------------------------------------------------------
__global__ void k_warp(const float* __restrict__ feat) {
    int x = threadIdx.x;
    int y = blockIdx.x;
    int b = blockIdx.y;
    int base = b*2*HWSZ + y*WW + x;
    float fx = (float)x + 2.5f * g_flow[base];
    float fy = (float)y + 2.5f * g_flow[base + HWSZ];
    float x0f = floorf(fx), y0f = floorf(fy);
    float wx1 = fx - x0f, wx0 = 1.f - wx1;
    float wy1 = fy - y0f, wy0 = 1.f - wy1;
    int x0 = (int)x0f, y0 = (int)y0f;
    int x1 = x0 + 1,  y1 = y0 + 1;
    bool vx0 = (x0 >= 0) & (x0 < WW), vx1 = (x1 >= 0) & (x1 < WW);
    bool vy0 = (y0 >= 0) & (y0 < HH), vy1 = (y1 >= 0) & (y1 < HH);
    float wa = wx0*wy0, wb = wx1*wy0, wc = wx0*wy1, wd = wx1*wy1;
    float m = wa*(float)(vx0&&vy0) + wb*(float)(vx1&&vy0)
            + wc*(float)(vx0&&vy1) + wd*(float)(vx1&&vy1);
    float mask = (m > 0.999f) ? 1.f : 0.f;
    float ea = (vx0&&vy0) ? wa*mask : 0.f;
    float eb = (vx1&&vy0) ? wb*mask : 0.f;
    float ec = (vx0&&vy1) ? wc*mask : 0.f;
    float ed = (vx1&&vy1) ? wd*mask : 0.f;
    int xa = min(max(x0,0),WW-1), xb = min(max(x1,0),WW-1);
    int ya = min(max(y0,0),HH-1), yb = min(max(y1,0),HH-1);
    const float* fp = feat + (size_t)b*CC_FEAT*HWSZ;
    int oa = ya*WW+xa, ob = ya*WW+xb, oc = yb*WW+xa, od = yb*WW+xb;
    float* outp = g_feat2 + (size_t)b*CC_FEAT*HWSZ + y*WW + x;
#pragma unroll 4
    for (int c = 0; c < CC_FEAT; c++) {
        float v = ea*fp[oa] + eb*fp[ob] + ec*fp[oc] + ed*fp[od];
        *outp = v;
        fp += HWSZ; outp += HWSZ;
    }
}

// ---------------------------------------------------------------------------
// correlation + leaky relu
// ---------------------------------------------------------------------------
__global__ void k_corr(const float* __restrict__ first) {
    const int tx = threadIdx.x, ty = threadIdx.y;
    const int x0 = blockIdx.x*32, y0 = blockIdx.y*8, b = blockIdx.z;
    __shared__ float s_f[4][8][32];
    __shared__ float s_p[4][14][40];
    float acc[49];
#pragma unroll
    for (int i = 0; i < 49; i++) acc[i] = 0.f;
    const int tid = ty*32 + tx;

    for (int c0 = 0; c0 < CC_FEAT; c0 += 4) {
#pragma unroll
        for (int cc = 0; cc < 4; cc++)
            s_f[cc][ty][tx] = first[((b*CC_FEAT + c0+cc)*HH + y0+ty)*WW + x0+tx];
        for (int i = tid; i < 4*14*38; i += 256) {
            int cc  = i / (14*38);
            int r   = (i / 38) % 14;
            int col = i % 38;
            int gy = y0 + r - 3, gx = x0 + col - 3;
            float v = 0.f;
            if (gy >= 0 && gy < HH && gx >= 0 && gx < WW)
                v = g_feat2[((b*CC_FEAT + c0+cc)*HH + gy)*WW + gx];
            s_p[cc][r][col] = v;
        }
        __syncthreads();
#pragma unroll
        for (int cc = 0; cc < 4; cc++) {
            float f = s_f[cc][ty][tx];
#pragma unroll
            for (int dy = 0; dy < 7; dy++)
#pragma unroll
                for (int dx = 0; dx < 7; dx++)
                    acc[dy*7+dx] += f * s_p[cc][ty+dy][tx+dx];
        }
        __syncthreads();
    }
    const float inv = 1.f/96.f;
#pragma unroll
    for (int d = 0; d < 49; d++) {
        float v = acc[d]*inv;
        v = (v >= 0.f) ? v : 0.1f*v;
        g_corr[((b*49 + d)*HH + y0+ty)*WW + x0+tx] = v;
    }
}

// ---------------------------------------------------------------------------
// final 5x5 conv (32->2) + bias + flow residual
// ---------------------------------------------------------------------------
__global__ void k_conv4(const float* __restrict__ wt, const float* __restrict__ bias,
                        float* __restrict__ out) {
    const int tx = threadIdx.x, ty = threadIdx.y;
    const int x0 = blockIdx.x*32, y0 = blockIdx.y*32;
    const int b = blockIdx.z;
    __shared__ float s_in[4][36][36];
    __shared__ float s_w[2][4][25];
    float acc[4][2];
#pragma unroll
    for (int p = 0; p < 4; p++) { acc[p][0] = 0.f; acc[p][1] = 0.f; }
    const int tid = ty*32 + tx;

    for (int c0 = 0; c0 < 32; c0 += 4) {
        if (tid < 200) {
            int co = tid/100, r = tid%100, ci = r/25, k = r%25;
            s_w[co][ci][k] = wt[(co*32 + c0+ci)*25 + k];
        }
        for (int i = tid; i < 4*36*36; i += 256) {
            int cc = i/(36*36), r = (i/36)%36, col = i%36;
            int gy = y0 + r - 2, gx = x0 + col - 2;
            float v = 0.f;
            if (gy >= 0 && gy < HH && gx >= 0 && gx < WW)
                v = g_x3[((b*32 + c0+cc)*HH + gy)*WW + gx];
            s_in[cc][r][col] = v;
        }
        __syncthreads();
        for (int ci = 0; ci < 4; ci++) {
#pragma unroll
            for (int k = 0; k < 25; k++) {
                const int ky = k/5, kx = k%5;
                float w0 = s_w[0][ci][k];
                float w1 = s_w[1][ci][k];
#pragma unroll
                for (int p = 0; p < 4; p++) {
                    float iv = s_in[ci][ty + 8*p + ky][tx + kx];
                    acc[p][0] += iv * w0;
                    acc[p][1] += iv * w1;
                }
            }
        }
        __syncthreads();
    }
#pragma unroll
    for (int co = 0; co < 2; co++) {
        float bs = bias[co];
#pragma unroll
        for (int p = 0; p < 4; p++) {
            int o = ((b*2 + co)*HH + y0 + ty + 8*p)*WW + x0 + tx;
            out[o] = g_flow[o] + bs + acc[p][co];
        }
    }
}

// ---------------------------------------------------------------------------
extern "C" void kernel_launch(void* const* d_in, const int* in_sizes, int n_in,
                              void* d_out, int out_size) {
    const float* featFirst  = (const float*)d_in[2];
    const float* featSecond = (const float*)d_in[3];
    const float* tflow      = (const float*)d_in[4];
    const float* wu         = (const float*)d_in[5];
    const float* w1 = (const float*)d_in[6];
    const float* b1 = (const float*)d_in[7];
    const float* w2 = (const float*)d_in[8];
    const float* b2 = (const float*)d_in[9];
    const float* w3 = (const float*)d_in[10];
    const float* b3 = (const float*)d_in[11];
    const float* w4 = (const float*)d_in[12];
    const float* b4 = (const float*)d_in[13];
    float* out = (float*)d_out;

    // dynamic smem sizes
    const int SM1 = (4*3*132*16*2)*2 + 2*2*128*16*2;   // 117760
    const int SM2 = (8*3*132*16*2)*2 + 2*2*64*16*2;    // 210944
    const int SM3 = (4*3*132*16*2)*2 + 2*2*32*16*2;    // 105472
    cudaFuncSetAttribute(k_conv1m, cudaFuncAttributeMaxDynamicSharedMemorySize, SM1);
    cudaFuncSetAttribute(k_conv2m, cudaFuncAttributeMaxDynamicSharedMemorySize, SM2);
    cudaFuncSetAttribute(k_conv3m, cudaFuncAttributeMaxDynamicSharedMemorySize, SM3);

    // weight prep (cheap, every call)
    __nv_bfloat16 *w1h, *w1l, *w2h, *w2l, *w3h, *w3l;
    cudaGetSymbolAddress((void**)&w1h, g_w1h); cudaGetSymbolAddress((void**)&w1l, g_w1l);
    cudaGetSymbolAddress((void**)&w2h, g_w2h); cudaGetSymbolAddress((void**)&w2l, g_w2l);
    cudaGetSymbolAddress((void**)&w3h, g_w3h); cudaGetSymbolAddress((void**)&w3l, g_w3l);
    k_wprep<<<288, 256>>>(w1, w1h, w1l, 128, 49, 64);
    k_wprep<<<288, 256>>>(w2, w2h, w2l, 64, 128, 128);
    k_wprep<<<72,  256>>>(w3, w3h, w3l, 32, 64, 64);

    k_upflow<<<512, 1024>>>(tflow, wu);
    k_warp<<<dim3(128, 16), 128>>>(featSecond);
    k_corr<<<dim3(4, 16, 16), dim3(32, 8)>>>(featFirst);
    k_conv1m<<<dim3(128, 16), 256, SM1>>>(b1);
    k_conv2m<<<dim3(128, 16), 256, SM2>>>(b2);
    k_conv3m<<<dim3(128, 16), 256, SM3>>>(b3);
    k_conv4<<<dim3(4, 4, 16), dim3(32, 8)>>>(w4, b4, out);
}

// round 8
// speedup vs baseline: 4.6177x; 1.7109x over previous
#include <cuda_runtime.h>
#include <cuda_bf16.h>

#define BB 16
#define CC_FEAT 96
#define HH 128
#define WW 128
#define HWSZ (HH*WW)

typedef unsigned int u32;

// ---- scratch (device globals; no allocation allowed) ----
__device__ float g_flow [BB*2  *HWSZ];
__device__ float g_feat2[BB*CC_FEAT*HWSZ];
__device__ float g_corr [BB*49 *HWSZ];
__device__ float g_x1   [BB*128*HWSZ];
__device__ float g_x2   [BB*64 *HWSZ];
__device__ float g_x3   [BB*32 *HWSZ];

// split bf16 weights: layout [(s9*NCHK+chunk)*COUT + co]*16 + k
__device__ __nv_bfloat16 g_w1h[9*4*128*16], g_w1l[9*4*128*16];
__device__ __nv_bfloat16 g_w2h[9*8*64*16],  g_w2l[9*8*64*16];
__device__ __nv_bfloat16 g_w3h[9*4*32*16],  g_w3l[9*4*32*16];

// split bf16 activations: layout [((b*NCHK+chunk)*HH+y)*WW+x]*16 + k
__device__ __nv_bfloat16 g_a0h[BB*4*HWSZ*16], g_a0l[BB*4*HWSZ*16];   // corr (49->64)
__device__ __nv_bfloat16 g_a1h[(size_t)BB*8*HWSZ*16], g_a1l[(size_t)BB*8*HWSZ*16]; // x1
__device__ __nv_bfloat16 g_a2h[BB*4*HWSZ*16], g_a2l[BB*4*HWSZ*16];   // x2

__device__ __forceinline__ void split_bf16(float x, unsigned short& h, unsigned short& l) {
    __nv_bfloat16 bh = __float2bfloat16(x);
    float r = x - __bfloat162float(bh);
    __nv_bfloat16 bl = __float2bfloat16(r);
    h = __bfloat16_as_ushort(bh);
    l = __bfloat16_as_ushort(bl);
}

__device__ __forceinline__ void mma_bf16(float* c, const u32* a, const u32* b) {
    asm volatile("mma.sync.aligned.m16n8k16.row.col.f32.bf16.bf16.f32 "
        "{%0,%1,%2,%3}, {%4,%5,%6,%7}, {%8,%9}, {%0,%1,%2,%3};"
        : "+f"(c[0]), "+f"(c[1]), "+f"(c[2]), "+f"(c[3])
        : "r"(a[0]), "r"(a[1]), "r"(a[2]), "r"(a[3]), "r"(b[0]), "r"(b[1]));
}

// ---------------------------------------------------------------------------
// weight prep: w[COUT][CIN][3][3] -> [(s9*NCHK+chunk)*COUT+co][16k] hi/lo
// ---------------------------------------------------------------------------
__global__ void k_wprep(const float* __restrict__ w, __nv_bfloat16* __restrict__ oh,
                        __nv_bfloat16* __restrict__ ol, int COUT, int CIN, int NCHK) {
    int idx = blockIdx.x*256 + threadIdx.x;
    if (idx >= 9*NCHK*COUT*16) return;
    int k  = idx & 15;
    int co = (idx >> 4) % COUT;
    int t  = (idx >> 4) / COUT;
    int chunk = t % NCHK, s9 = t / NCHK;
    int ci = chunk*16 + k;
    float v = (ci < CIN) ? w[(co*CIN + ci)*9 + s9] : 0.f;
    unsigned short h, l;
    split_bf16(v, h, l);
    oh[idx] = __ushort_as_bfloat16(h);
    ol[idx] = __ushort_as_bfloat16(l);
}

// ---------------------------------------------------------------------------
// activation converter: fp32 [B][C][H][W] -> chunk16 hi/lo bf16
// ---------------------------------------------------------------------------
template<int CIN, int NCHK>
__global__ void k_cvt(const float* __restrict__ src, __nv_bfloat16* __restrict__ oh,
                      __nv_bfloat16* __restrict__ ol) {
    int idx = blockIdx.x*256 + threadIdx.x;
    int x = idx & 127, y = (idx >> 7) & 127;
    int chunk = (idx >> 14) % NCHK;
    int b = (idx >> 14) / NCHK;
    u32 ph[8], pl[8];
#pragma unroll
    for (int kp = 0; kp < 8; kp++) {
        int c0 = chunk*16 + kp*2;
        float v0 = (c0     < CIN) ? src[((size_t)(b*CIN + c0  )*HH + y)*WW + x] : 0.f;
        float v1 = (c0 + 1 < CIN) ? src[((size_t)(b*CIN + c0+1)*HH + y)*WW + x] : 0.f;
        unsigned short h0, l0, h1, l1;
        split_bf16(v0, h0, l0);
        split_bf16(v1, h1, l1);
        ph[kp] = ((u32)h1 << 16) | h0;
        pl[kp] = ((u32)l1 << 16) | l0;
    }
    size_t o = ((((size_t)b*NCHK + chunk)*HH + y)*WW + x)*16;
    ((uint4*)(oh + o))[0] = make_uint4(ph[0], ph[1], ph[2], ph[3]);
    ((uint4*)(oh + o))[1] = make_uint4(ph[4], ph[5], ph[6], ph[7]);
    ((uint4*)(ol + o))[0] = make_uint4(pl[0], pl[1], pl[2], pl[3]);
    ((uint4*)(ol + o))[1] = make_uint4(pl[4], pl[5], pl[6], pl[7]);
}

// ---------------------------------------------------------------------------
// MMA conv: 3x3 pad1 conv = 9 shifted GEMMs, bf16 hi/lo split (3 mma/step).
// Block = one output row y, one batch. A (weights) loaded from global (L1),
// B staged in smem in chunk-groups of 4; no barriers inside the MMA loop.
// ---------------------------------------------------------------------------
template<int COUT, int NCHK, int WGM, int WGN, int WM, int WN>
__device__ __forceinline__ void convmma_body(
        const u32* __restrict__ whp, const u32* __restrict__ wlp,
        const __nv_bfloat16* __restrict__ ghi, const __nv_bfloat16* __restrict__ glo,
        const float* __restrict__ bias, float* __restrict__ out) {
    const int GC = 4;
    const int tid = threadIdx.x;
    const int lane = tid & 31, warp = tid >> 5;
    const int wm = warp % WGM, wn = warp / WGM;
    const int y = blockIdx.x, b = blockIdx.y;
    const int m_base = wm * (WM*16);
    const int n_base = wn * (WN*8);
    const int gid = lane >> 3 ? (lane >> 2) : (lane >> 2);   // groupID = lane>>2
    const int grp = lane >> 2;
    const int kq  = lane & 3;            // k quad (u32 index)
    const int k0  = kq * 2;              // bf16 element index

    extern __shared__ char smraw[];
    __nv_bfloat16* s_bh = (__nv_bfloat16*)smraw;
    __nv_bfloat16* s_bl = s_bh + GC*3*132*16;

    float acc[WM][WN][4];
#pragma unroll
    for (int mi = 0; mi < WM; mi++)
#pragma unroll
        for (int fi = 0; fi < WN; fi++)
#pragma unroll
            for (int q = 0; q < 4; q++) acc[mi][fi][q] = 0.f;

    for (int g = 0; g < NCHK; g += GC) {
        if (g) __syncthreads();
        // ---- stage B group: pure vectorized copy from pre-split tensors ----
        {
            const int NU = GC*3*130*2;   // 32B units
            for (int u = tid; u < NU; u += 256) {
                int hl = u / (GC*3*130);
                int v  = u % (GC*3*130);
                int col = v % 130;
                int t   = v / 130;
                int row = t % 3, c = t / 3;
                int gx = col - 1, gy = y + row - 1;
                uint4 z0 = make_uint4(0,0,0,0), z1 = z0;
                if (gy >= 0 && gy < HH && gx >= 0 && gx < WW) {
                    const __nv_bfloat16* gsrc = hl ? glo : ghi;
                    const uint4* p = (const uint4*)(gsrc +
                        ((((size_t)b*NCHK + (g + c))*HH + gy)*WW + gx)*16);
                    z0 = p[0]; z1 = p[1];
                }
                __nv_bfloat16* sdst = (hl ? s_bl : s_bh) + ((c*3 + row)*132 + col)*16;
                ((uint4*)sdst)[0] = z0;
                ((uint4*)sdst)[1] = z1;
            }
        }
        __syncthreads();

        // ---- MMA loop: no barriers ----
        for (int c = 0; c < GC; c++) {
            int chunk = g + c;
#pragma unroll
            for (int s9 = 0; s9 < 9; s9++) {
                const int ky = s9 / 3, kx = s9 % 3;
                const u32* wb_h = whp + (size_t)((s9*NCHK + chunk)*COUT)*8;
                const u32* wb_l = wlp + (size_t)((s9*NCHK + chunk)*COUT)*8;
                u32 a_h[WM][4], a_l[WM][4];
#pragma unroll
                for (int mi = 0; mi < WM; mi++) {
                    int r0 = m_base + mi*16 + grp;
                    a_h[mi][0] = wb_h[(r0    )*8 + kq    ];
                    a_h[mi][1] = wb_h[(r0 + 8)*8 + kq    ];
                    a_h[mi][2] = wb_h[(r0    )*8 + kq + 4];
                    a_h[mi][3] = wb_h[(r0 + 8)*8 + kq + 4];
                    a_l[mi][0] = wb_l[(r0    )*8 + kq    ];
                    a_l[mi][1] = wb_l[(r0 + 8)*8 + kq    ];
                    a_l[mi][2] = wb_l[(r0    )*8 + kq + 4];
                    a_l[mi][3] = wb_l[(r0 + 8)*8 + kq + 4];
                }
                const __nv_bfloat16* bh_row = s_bh + ((c*3 + ky)*132)*16;
                const __nv_bfloat16* bl_row = s_bl + ((c*3 + ky)*132)*16;
#pragma unroll
                for (int fi = 0; fi < WN; fi++) {
                    int coln = n_base + fi*8 + grp + kx;
                    u32 b_h[2], b_l[2];
                    b_h[0] = *(const u32*)&bh_row[coln*16 + k0    ];
                    b_h[1] = *(const u32*)&bh_row[coln*16 + k0 + 8];
                    b_l[0] = *(const u32*)&bl_row[coln*16 + k0    ];
                    b_l[1] = *(const u32*)&bl_row[coln*16 + k0 + 8];
#pragma unroll
                    for (int mi = 0; mi < WM; mi++) {
                        mma_bf16(acc[mi][fi], a_h[mi], b_h);
                        mma_bf16(acc[mi][fi], a_l[mi], b_h);
                        mma_bf16(acc[mi][fi], a_h[mi], b_l);
                    }
                }
            }
        }
    }

    // ---- epilogue: bias + leaky relu + fp32 store ----
    (void)gid;
#pragma unroll
    for (int mi = 0; mi < WM; mi++) {
        int r0 = m_base + mi*16 + grp;
        float bi0 = bias[r0], bi1 = bias[r0 + 8];
#pragma unroll
        for (int fi = 0; fi < WN; fi++) {
            int n = n_base + fi*8 + kq*2;
            float d0 = acc[mi][fi][0] + bi0;
            float d1 = acc[mi][fi][1] + bi0;
            float d2 = acc[mi][fi][2] + bi1;
            float d3 = acc[mi][fi][3] + bi1;
            d0 = (d0 >= 0.f) ? d0 : 0.1f*d0;
            d1 = (d1 >= 0.f) ? d1 : 0.1f*d1;
            d2 = (d2 >= 0.f) ? d2 : 0.1f*d2;
            d3 = (d3 >= 0.f) ? d3 : 0.1f*d3;
            *(float2*)&out[((size_t)(b*COUT + r0    )*HH + y)*WW + n] = make_float2(d0, d1);
            *(float2*)&out[((size_t)(b*COUT + r0 + 8)*HH + y)*WW + n] = make_float2(d2, d3);
        }
    }
}

__global__ void __launch_bounds__(256, 2)
k_conv1m(const float* __restrict__ bias) {
    convmma_body<128, 4, 4, 2, 2, 8>((const u32*)g_w1h, (const u32*)g_w1l,
                                     g_a0h, g_a0l, bias, g_x1);
}
__global__ void __launch_bounds__(256, 2)
k_conv2m(const float* __restrict__ bias) {
    convmma_body<64, 8, 2, 4, 2, 4>((const u32*)g_w2h, (const u32*)g_w2l,
                                    g_a1h, g_a1l, bias, g_x2);
}
__global__ void __launch_bounds__(256, 2)
k_conv3m(const float* __restrict__ bias) {
    convmma_body<32, 4, 2, 4, 1, 4>((const u32*)g_w3h, (const u32*)g_w3l,
                                    g_a2h, g_a2l, bias, g_x3);
}

// ---------------------------------------------------------------------------
// upflow
// ---------------------------------------------------------------------------
__global__ void k_upflow(const float* __restrict__ tf, const float* __restrict__ wu) {
    int idx = blockIdx.x * blockDim.x + threadIdx.x;
    int ox = idx & 127, oy = (idx >> 7) & 127, c = (idx >> 14) & 1, b = idx >> 15;
    float acc = 0.f;
#pragma unroll
    for (int ky = 0; ky < 4; ky++) {
        int iy = oy + ky - 2;
        if (iy < 0 || iy > 126 || (iy & 1)) continue;
        iy >>= 1;
#pragma unroll
        for (int kx = 0; kx < 4; kx++) {
            int ix = ox + kx - 2;
            if (ix < 0 || ix > 126 || (ix & 1)) continue;
            ix >>= 1;
            acc += wu[c*16 + (3-ky)*4 + (3-kx)] * tf[((b*2 + c)*64 + iy)*64 + ix];
        }
    }
    g_flow[idx] = acc;
}

// ---------------------------------------------------------------------------
// backward warp
// ---------------------------------------------------------------------------
__global__ void k_warp(const float* __restrict__ feat) {
    int x = threadIdx.x;
    int y = blockIdx.x;
    int b = blockIdx.y;
    int base = b*2*HWSZ + y*WW + x;
    float fx = (float)x + 2.5f * g_flow[base];
    float fy = (float)y + 2.5f * g_flow[base + HWSZ];
    float x0f = floorf(fx), y0f = floorf(fy);
    float wx1 = fx - x0f, wx0 = 1.f - wx1;
    float wy1 = fy - y0f, wy0 = 1.f - wy1;
    int x0 = (int)x0f, y0 = (int)y0f;
    int x1 = x0 + 1,  y1 = y0 + 1;
    bool vx0 = (x0 >= 0) & (x0 < WW), vx1 = (x1 >= 0) & (x1 < WW);
    bool vy0 = (y0 >= 0) & (y0 < HH), vy1 = (y1 >= 0) & (y1 < HH);
    float wa = wx0*wy0, wb = wx1*wy0, wc = wx0*wy1, wd = wx1*wy1;
    float m = wa*(float)(vx0&&vy0) + wb*(float)(vx1&&vy0)
            + wc*(float)(vx0&&vy1) + wd*(float)(vx1&&vy1);
    float mask = (m > 0.999f) ? 1.f : 0.f;
    float ea = (vx0&&vy0) ? wa*mask : 0.f;
    float eb = (vx1&&vy0) ? wb*mask : 0.f;
    float ec = (vx0&&vy1) ? wc*mask : 0.f;
    float ed = (vx1&&vy1) ? wd*mask : 0.f;
    int xa = min(max(x0,0),WW-1), xb = min(max(x1,0),WW-1);
    int ya = min(max(y0,0),HH-1), yb = min(max(y1,0),HH-1);
    const float* fp = feat + (size_t)b*CC_FEAT*HWSZ;
    int oa = ya*WW+xa, ob = ya*WW+xb, oc = yb*WW+xa, od = yb*WW+xb;
    float* outp = g_feat2 + (size_t)b*CC_FEAT*HWSZ + y*WW + x;
#pragma unroll 4
    for (int c = 0; c < CC_FEAT; c++) {
        float v = ea*fp[oa] + eb*fp[ob] + ec*fp[oc] + ed*fp[od];
        *outp = v;
        fp += HWSZ; outp += HWSZ;
    }
}

// ---------------------------------------------------------------------------
// correlation + leaky relu
// ---------------------------------------------------------------------------
__global__ void k_corr(const float* __restrict__ first) {
    const int tx = threadIdx.x, ty = threadIdx.y;
    const int x0 = blockIdx.x*32, y0 = blockIdx.y*8, b = blockIdx.z;
    __shared__ float s_f[4][8][32];
    __shared__ float s_p[4][14][40];
    float acc[49];
#pragma unroll
    for (int i = 0; i < 49; i++) acc[i] = 0.f;
    const int tid = ty*32 + tx;

    for (int c0 = 0; c0 < CC_FEAT; c0 += 4) {
#pragma unroll
        for (int cc = 0; cc < 4; cc++)
            s_f[cc][ty][tx] = first[((b*CC_FEAT + c0+cc)*HH + y0+ty)*WW + x0+tx];
        for (int i = tid; i < 4*14*38; i += 256) {
            int cc  = i / (14*38);
            int r   = (i / 38) % 14;
            int col = i % 38;
            int gy = y0 + r - 3, gx = x0 + col - 3;
            float v = 0.f;
            if (gy >= 0 && gy < HH && gx >= 0 && gx < WW)
                v = g_feat2[((b*CC_FEAT + c0+cc)*HH + gy)*WW + gx];
            s_p[cc][r][col] = v;
        }
        __syncthreads();
#pragma unroll
        for (int cc = 0; cc < 4; cc++) {
            float f = s_f[cc][ty][tx];
#pragma unroll
            for (int dy = 0; dy < 7; dy++)
#pragma unroll
                for (int dx = 0; dx < 7; dx++)
                    acc[dy*7+dx] += f * s_p[cc][ty+dy][tx+dx];
        }
        __syncthreads();
    }
    const float inv = 1.f/96.f;
#pragma unroll
    for (int d = 0; d < 49; d++) {
        float v = acc[d]*inv;
        v = (v >= 0.f) ? v : 0.1f*v;
        g_corr[((b*49 + d)*HH + y0+ty)*WW + x0+tx] = v;
    }
}

// ---------------------------------------------------------------------------
// final 5x5 conv (32->2) + bias + flow residual
// ---------------------------------------------------------------------------
__global__ void k_conv4(const float* __restrict__ wt, const float* __restrict__ bias,
                        float* __restrict__ out) {
    const int tx = threadIdx.x, ty = threadIdx.y;
    const int x0 = blockIdx.x*32, y0 = blockIdx.y*32;
    const int b = blockIdx.z;
    __shared__ float s_in[4][36][36];
    __shared__ float s_w[2][4][25];
    float acc[4][2];
#pragma unroll
    for (int p = 0; p < 4; p++) { acc[p][0] = 0.f; acc[p][1] = 0.f; }
    const int tid = ty*32 + tx;

    for (int c0 = 0; c0 < 32; c0 += 4) {
        if (tid < 200) {
            int co = tid/100, r = tid%100, ci = r/25, k = r%25;
            s_w[co][ci][k] = wt[(co*32 + c0+ci)*25 + k];
        }
        for (int i = tid; i < 4*36*36; i += 256) {
            int cc = i/(36*36), r = (i/36)%36, col = i%36;
            int gy = y0 + r - 2, gx = x0 + col - 2;
            float v = 0.f;
            if (gy >= 0 && gy < HH && gx >= 0 && gx < WW)
                v = g_x3[((b*32 + c0+cc)*HH + gy)*WW + gx];
            s_in[cc][r][col] = v;
        }
        __syncthreads();
        for (int ci = 0; ci < 4; ci++) {
#pragma unroll
            for (int k = 0; k < 25; k++) {
                const int ky = k/5, kx = k%5;
                float w0 = s_w[0][ci][k];
                float w1 = s_w[1][ci][k];
#pragma unroll
                for (int p = 0; p < 4; p++) {
                    float iv = s_in[ci][ty + 8*p + ky][tx + kx];
                    acc[p][0] += iv * w0;
                    acc[p][1] += iv * w1;
                }
            }
        }
        __syncthreads();
    }
#pragma unroll
    for (int co = 0; co < 2; co++) {
        float bs = bias[co];
#pragma unroll
        for (int p = 0; p < 4; p++) {
            int o = ((b*2 + co)*HH + y0 + ty + 8*p)*WW + x0 + tx;
            out[o] = g_flow[o] + bs + acc[p][co];
        }
    }
}

// ---------------------------------------------------------------------------
extern "C" void kernel_launch(void* const* d_in, const int* in_sizes, int n_in,
                              void* d_out, int out_size) {
    const float* featFirst  = (const float*)d_in[2];
    const float* featSecond = (const float*)d_in[3];
    const float* tflow      = (const float*)d_in[4];
    const float* wu         = (const float*)d_in[5];
    const float* w1 = (const float*)d_in[6];
    const float* b1 = (const float*)d_in[7];
    const float* w2 = (const float*)d_in[8];
    const float* b2 = (const float*)d_in[9];
    const float* w3 = (const float*)d_in[10];
    const float* b3 = (const float*)d_in[11];
    const float* w4 = (const float*)d_in[12];
    const float* b4 = (const float*)d_in[13];
    float* out = (float*)d_out;

    const int SMB = 4*3*132*16*2*2;   // 101376 bytes (hi+lo)
    static int attr_done = 0;
    cudaFuncSetAttribute(k_conv1m, cudaFuncAttributeMaxDynamicSharedMemorySize, SMB);
    cudaFuncSetAttribute(k_conv2m, cudaFuncAttributeMaxDynamicSharedMemorySize, SMB);
    cudaFuncSetAttribute(k_conv3m, cudaFuncAttributeMaxDynamicSharedMemorySize, SMB);
    (void)attr_done;

    __nv_bfloat16 *w1h, *w1l, *w2h, *w2l, *w3h, *w3l;
    __nv_bfloat16 *a0h, *a0l, *a1h, *a1l, *a2h, *a2l;
    cudaGetSymbolAddress((void**)&w1h, g_w1h); cudaGetSymbolAddress((void**)&w1l, g_w1l);
    cudaGetSymbolAddress((void**)&w2h, g_w2h); cudaGetSymbolAddress((void**)&w2l, g_w2l);
    cudaGetSymbolAddress((void**)&w3h, g_w3h); cudaGetSymbolAddress((void**)&w3l, g_w3l);
    cudaGetSymbolAddress((void**)&a0h, g_a0h); cudaGetSymbolAddress((void**)&a0l, g_a0l);
    cudaGetSymbolAddress((void**)&a1h, g_a1h); cudaGetSymbolAddress((void**)&a1l, g_a1l);
    cudaGetSymbolAddress((void**)&a2h, g_a2h); cudaGetSymbolAddress((void**)&a2l, g_a2l);

    float *p_corr, *p_x1, *p_x2;
    cudaGetSymbolAddress((void**)&p_corr, g_corr);
    cudaGetSymbolAddress((void**)&p_x1,   g_x1);
    cudaGetSymbolAddress((void**)&p_x2,   g_x2);

    // weight prep
    k_wprep<<<288, 256>>>(w1, w1h, w1l, 128, 49, 4);
    k_wprep<<<288, 256>>>(w2, w2h, w2l, 64, 128, 8);
    k_wprep<<<72,  256>>>(w3, w3h, w3l, 32, 64, 4);

    k_upflow<<<512, 1024>>>(tflow, wu);
    k_warp<<<dim3(128, 16), 128>>>(featSecond);
    k_corr<<<dim3(4, 16, 16), dim3(32, 8)>>>(featFirst);

    k_cvt<49, 4><<<4096, 256>>>(p_corr, a0h, a0l);
    k_conv1m<<<dim3(128, 16), 256, SMB>>>(b1);
    k_cvt<128, 8><<<8192, 256>>>(p_x1, a1h, a1l);
    k_conv2m<<<dim3(128, 16), 256, SMB>>>(b2);
    k_cvt<64, 4><<<4096, 256>>>(p_x2, a2h, a2l);
    k_conv3m<<<dim3(128, 16), 256, SMB>>>(b3);
    k_conv4<<<dim3(4, 4, 16), dim3(32, 8)>>>(w4, b4, out);
}

// round 9
// speedup vs baseline: 5.2478x; 1.1364x over previous
#include <cuda_runtime.h>
#include <cuda_bf16.h>

#define BB 16
#define CC_FEAT 96
#define HH 128
#define WW 128
#define HWSZ (HH*WW)

typedef unsigned int u32;

// ---- scratch (device globals; no allocation allowed) ----
__device__ float g_flow [BB*2  *HWSZ];
__device__ float g_feat2[BB*CC_FEAT*HWSZ];
__device__ float g_x3   [BB*32 *HWSZ];

// split bf16 weights: layout [(s9*NCHK+chunk)*COUT + co]*16 + k
__device__ __nv_bfloat16 g_w1h[9*4*128*16], g_w1l[9*4*128*16];
__device__ __nv_bfloat16 g_w2h[9*8*64*16],  g_w2l[9*8*64*16];
__device__ __nv_bfloat16 g_w3h[9*4*32*16],  g_w3l[9*4*32*16];

// split bf16 activations: layout [((b*NCHK+chunk)*HH+y)*WW+x]*16 + k
__device__ __nv_bfloat16 g_a0h[BB*4*HWSZ*16], g_a0l[BB*4*HWSZ*16];                  // corr
__device__ __nv_bfloat16 g_a1h[(size_t)BB*8*HWSZ*16], g_a1l[(size_t)BB*8*HWSZ*16]; // x1
__device__ __nv_bfloat16 g_a2h[BB*4*HWSZ*16], g_a2l[BB*4*HWSZ*16];                  // x2

__device__ __forceinline__ void split_bf16(float x, unsigned short& h, unsigned short& l) {
    __nv_bfloat16 bh = __float2bfloat16(x);
    float r = x - __bfloat162float(bh);
    __nv_bfloat16 bl = __float2bfloat16(r);
    h = __bfloat16_as_ushort(bh);
    l = __bfloat16_as_ushort(bl);
}

__device__ __forceinline__ void mma_bf16(float* c, const u32* a, const u32* b) {
    asm volatile("mma.sync.aligned.m16n8k16.row.col.f32.bf16.bf16.f32 "
        "{%0,%1,%2,%3}, {%4,%5,%6,%7}, {%8,%9}, {%0,%1,%2,%3};"
        : "+f"(c[0]), "+f"(c[1]), "+f"(c[2]), "+f"(c[3])
        : "r"(a[0]), "r"(a[1]), "r"(a[2]), "r"(a[3]), "r"(b[0]), "r"(b[1]));
}

// ---------------------------------------------------------------------------
// weight prep
// ---------------------------------------------------------------------------
__global__ void k_wprep(const float* __restrict__ w, __nv_bfloat16* __restrict__ oh,
                        __nv_bfloat16* __restrict__ ol, int COUT, int CIN, int NCHK) {
    int idx = blockIdx.x*256 + threadIdx.x;
    if (idx >= 9*NCHK*COUT*16) return;
    int k  = idx & 15;
    int co = (idx >> 4) % COUT;
    int t  = (idx >> 4) / COUT;
    int chunk = t % NCHK, s9 = t / NCHK;
    int ci = chunk*16 + k;
    float v = (ci < CIN) ? w[(co*CIN + ci)*9 + s9] : 0.f;
    unsigned short h, l;
    split_bf16(v, h, l);
    oh[idx] = __ushort_as_bfloat16(h);
    ol[idx] = __ushort_as_bfloat16(l);
}

// ---------------------------------------------------------------------------
// MMA conv: 3x3 pad1 conv = 9 shifted GEMMs, bf16 hi/lo split.
// A (weights) from global (L1-resident), B staged in smem with XOR-4 swizzle.
// SPLITOUT: epilogue re-layouts output through smem into chunk16 hi/lo bf16.
// ---------------------------------------------------------------------------
template<int COUT, int NCHK, int NCHKO, int WGM, int WGN, int WM, int WN, bool SPLITOUT>
__device__ __forceinline__ void convmma_body(
        const u32* __restrict__ whp, const u32* __restrict__ wlp,
        const __nv_bfloat16* __restrict__ ghi, const __nv_bfloat16* __restrict__ glo,
        const float* __restrict__ bias,
        float* __restrict__ outf,
        __nv_bfloat16* __restrict__ outh, __nv_bfloat16* __restrict__ outl) {
    const int GC = 4;
    const int tid = threadIdx.x;
    const int lane = tid & 31, warp = tid >> 5;
    const int wm = warp % WGM, wn = warp / WGM;
    const int y = blockIdx.x, b = blockIdx.y;
    const int m_base = wm * (WM*16);
    const int n_base = wn * (WN*8);
    const int grp = lane >> 2;
    const int kq  = lane & 3;

    extern __shared__ char smraw[];
    __nv_bfloat16* s_bh = (__nv_bfloat16*)smraw;
    __nv_bfloat16* s_bl = s_bh + GC*3*132*16;

    float acc[WM][WN][4];
#pragma unroll
    for (int mi = 0; mi < WM; mi++)
#pragma unroll
        for (int fi = 0; fi < WN; fi++)
#pragma unroll
            for (int q = 0; q < 4; q++) acc[mi][fi][q] = 0.f;

    for (int g = 0; g < NCHK; g += GC) {
        if (g) __syncthreads();
        // ---- stage B group (vectorized copy + XOR-4 swizzle on u32 index) ----
        {
            const int NU = GC*3*130*2;
            for (int u = tid; u < NU; u += 256) {
                int hl = u / (GC*3*130);
                int v  = u % (GC*3*130);
                int col = v % 130;
                int t   = v / 130;
                int row = t % 3, c = t / 3;
                int gx = col - 1, gy = y + row - 1;
                uint4 z0 = make_uint4(0,0,0,0), z1 = z0;
                if (gy >= 0 && gy < HH && gx >= 0 && gx < WW) {
                    const __nv_bfloat16* gsrc = hl ? glo : ghi;
                    const uint4* p = (const uint4*)(gsrc +
                        ((((size_t)b*NCHK + (g + c))*HH + gy)*WW + gx)*16);
                    z0 = p[0]; z1 = p[1];
                }
                int sw = (col >> 2) & 1;
                uint4* sdst = (uint4*)((hl ? s_bl : s_bh) + ((c*3 + row)*132 + col)*16);
                sdst[sw]     = z0;
                sdst[sw ^ 1] = z1;
            }
        }
        __syncthreads();

        // ---- MMA loop: no barriers ----
        for (int c = 0; c < GC; c++) {
            int chunk = g + c;
#pragma unroll
            for (int s9 = 0; s9 < 9; s9++) {
                const int ky = s9 / 3, kx = s9 % 3;
                const u32* wb_h = whp + (size_t)((s9*NCHK + chunk)*COUT)*8;
                const u32* wb_l = wlp + (size_t)((s9*NCHK + chunk)*COUT)*8;
                u32 a_h[WM][4], a_l[WM][4];
#pragma unroll
                for (int mi = 0; mi < WM; mi++) {
                    int r0 = m_base + mi*16 + grp;
                    a_h[mi][0] = wb_h[(r0    )*8 + kq    ];
                    a_h[mi][1] = wb_h[(r0 + 8)*8 + kq    ];
                    a_h[mi][2] = wb_h[(r0    )*8 + kq + 4];
                    a_h[mi][3] = wb_h[(r0 + 8)*8 + kq + 4];
                    a_l[mi][0] = wb_l[(r0    )*8 + kq    ];
                    a_l[mi][1] = wb_l[(r0 + 8)*8 + kq    ];
                    a_l[mi][2] = wb_l[(r0    )*8 + kq + 4];
                    a_l[mi][3] = wb_l[(r0 + 8)*8 + kq + 4];
                }
                const u32* bh_row = (const u32*)(s_bh + ((c*3 + ky)*132)*16);
                const u32* bl_row = (const u32*)(s_bl + ((c*3 + ky)*132)*16);
#pragma unroll
                for (int fi = 0; fi < WN; fi++) {
                    int coln = n_base + fi*8 + grp + kx;
                    int swj = ((coln >> 2) & 1) * 4;
                    u32 b_h[2], b_l[2];
                    b_h[0] = bh_row[coln*8 + (kq ^ swj)];
                    b_h[1] = bh_row[coln*8 + ((kq + 4) ^ swj)];
                    b_l[0] = bl_row[coln*8 + (kq ^ swj)];
                    b_l[1] = bl_row[coln*8 + ((kq + 4) ^ swj)];
#pragma unroll
                    for (int mi = 0; mi < WM; mi++) {
                        mma_bf16(acc[mi][fi], a_h[mi], b_h);
                        mma_bf16(acc[mi][fi], a_l[mi], b_h);
                        mma_bf16(acc[mi][fi], a_h[mi], b_l);
                    }
                }
            }
        }
    }

    // ---- epilogue ----
    if (!SPLITOUT) {
#pragma unroll
        for (int mi = 0; mi < WM; mi++) {
            int r0 = m_base + mi*16 + grp;
            float bi0 = bias[r0], bi1 = bias[r0 + 8];
#pragma unroll
            for (int fi = 0; fi < WN; fi++) {
                int n = n_base + fi*8 + kq*2;
                float d0 = acc[mi][fi][0] + bi0;
                float d1 = acc[mi][fi][1] + bi0;
                float d2 = acc[mi][fi][2] + bi1;
                float d3 = acc[mi][fi][3] + bi1;
                d0 = (d0 >= 0.f) ? d0 : 0.1f*d0;
                d1 = (d1 >= 0.f) ? d1 : 0.1f*d1;
                d2 = (d2 >= 0.f) ? d2 : 0.1f*d2;
                d3 = (d3 >= 0.f) ? d3 : 0.1f*d3;
                *(float2*)&outf[((size_t)(b*COUT + r0    )*HH + y)*WW + n] = make_float2(d0, d1);
                *(float2*)&outf[((size_t)(b*COUT + r0 + 8)*HH + y)*WW + n] = make_float2(d2, d3);
            }
        }
    } else {
        __syncthreads();   // smem reuse for output staging
        __nv_bfloat16* s_oh = (__nv_bfloat16*)smraw;       // [NCHKO][WW][16]
        __nv_bfloat16* s_ol = s_oh + COUT*WW;
#pragma unroll
        for (int mi = 0; mi < WM; mi++) {
            int r0 = m_base + mi*16 + grp;
            float bi0 = bias[r0], bi1 = bias[r0 + 8];
#pragma unroll
            for (int fi = 0; fi < WN; fi++) {
                int n = n_base + fi*8 + kq*2;
#pragma unroll
                for (int q = 0; q < 4; q++) {
                    int co = (q < 2) ? r0 : r0 + 8;
                    float d = acc[mi][fi][q] + ((q < 2) ? bi0 : bi1);
                    d = (d >= 0.f) ? d : 0.1f*d;
                    unsigned short h, l;
                    split_bf16(d, h, l);
                    int xx = n + (q & 1);
                    int si = (co >> 4)*(WW*16) + xx*16 + (co & 15);
                    s_oh[si] = __ushort_as_bfloat16(h);
                    s_ol[si] = __ushort_as_bfloat16(l);
                }
            }
        }
        __syncthreads();
        // coalesced writeout: per chunk, WW*16 bf16 contiguous in both smem & gmem
        const int NU4 = COUT*WW/8;     // uint4 units
        for (int i = tid; i < NU4; i += 256) {
            int chunk = i >> 8;        // 256 uint4 per chunk (WW*16/8)
            int r = i & 255;
            size_t gbase = ((((size_t)b*NCHKO + chunk)*HH + y)*WW)*16;
            ((uint4*)(outh + gbase))[r] = ((const uint4*)(s_oh + chunk*(WW*16)))[r];
            ((uint4*)(outl + gbase))[r] = ((const uint4*)(s_ol + chunk*(WW*16)))[r];
        }
    }
}

__global__ void __launch_bounds__(256, 2)
k_conv1m(const float* __restrict__ bias) {
    convmma_body<128, 4, 8, 4, 2, 2, 8, true>((const u32*)g_w1h, (const u32*)g_w1l,
        g_a0h, g_a0l, bias, nullptr, g_a1h, g_a1l);
}
__global__ void __launch_bounds__(256, 2)
k_conv2m(const float* __restrict__ bias) {
    convmma_body<64, 8, 4, 2, 4, 2, 4, true>((const u32*)g_w2h, (const u32*)g_w2l,
        g_a1h, g_a1l, bias, nullptr, g_a2h, g_a2l);
}
__global__ void __launch_bounds__(256, 2)
k_conv3m(const float* __restrict__ bias) {
    convmma_body<32, 4, 2, 2, 4, 1, 4, false>((const u32*)g_w3h, (const u32*)g_w3l,
        g_a2h, g_a2l, bias, g_x3, nullptr, nullptr);
}

// ---------------------------------------------------------------------------
// upflow
// ---------------------------------------------------------------------------
__global__ void k_upflow(const float* __restrict__ tf, const float* __restrict__ wu) {
    int idx = blockIdx.x * blockDim.x + threadIdx.x;
    int ox = idx & 127, oy = (idx >> 7) & 127, c = (idx >> 14) & 1, b = idx >> 15;
    float acc = 0.f;
#pragma unroll
    for (int ky = 0; ky < 4; ky++) {
        int iy = oy + ky - 2;
        if (iy < 0 || iy > 126 || (iy & 1)) continue;
        iy >>= 1;
#pragma unroll
        for (int kx = 0; kx < 4; kx++) {
            int ix = ox + kx - 2;
            if (ix < 0 || ix > 126 || (ix & 1)) continue;
            ix >>= 1;
            acc += wu[c*16 + (3-ky)*4 + (3-kx)] * tf[((b*2 + c)*64 + iy)*64 + ix];
        }
    }
    g_flow[idx] = acc;
}

// ---------------------------------------------------------------------------
// backward warp
// ---------------------------------------------------------------------------
__global__ void k_warp(const float* __restrict__ feat) {
    int x = threadIdx.x;
    int y = blockIdx.x;
    int b = blockIdx.y;
    int base = b*2*HWSZ + y*WW + x;
    float fx = (float)x + 2.5f * g_flow[base];
    float fy = (float)y + 2.5f * g_flow[base + HWSZ];
    float x0f = floorf(fx), y0f = floorf(fy);
    float wx1 = fx - x0f, wx0 = 1.f - wx1;
    float wy1 = fy - y0f, wy0 = 1.f - wy1;
    int x0 = (int)x0f, y0 = (int)y0f;
    int x1 = x0 + 1,  y1 = y0 + 1;
    bool vx0 = (x0 >= 0) & (x0 < WW), vx1 = (x1 >= 0) & (x1 < WW);
    bool vy0 = (y0 >= 0) & (y0 < HH), vy1 = (y1 >= 0) & (y1 < HH);
    float wa = wx0*wy0, wb = wx1*wy0, wc = wx0*wy1, wd = wx1*wy1;
    float m = wa*(float)(vx0&&vy0) + wb*(float)(vx1&&vy0)
            + wc*(float)(vx0&&vy1) + wd*(float)(vx1&&vy1);
    float mask = (m > 0.999f) ? 1.f : 0.f;
    float ea = (vx0&&vy0) ? wa*mask : 0.f;
    float eb = (vx1&&vy0) ? wb*mask : 0.f;
    float ec = (vx0&&vy1) ? wc*mask : 0.f;
    float ed = (vx1&&vy1) ? wd*mask : 0.f;
    int xa = min(max(x0,0),WW-1), xb = min(max(x1,0),WW-1);
    int ya = min(max(y0,0),HH-1), yb = min(max(y1,0),HH-1);
    const float* fp = feat + (size_t)b*CC_FEAT*HWSZ;
    int oa = ya*WW+xa, ob = ya*WW+xb, oc = yb*WW+xa, od = yb*WW+xb;
    float* outp = g_feat2 + (size_t)b*CC_FEAT*HWSZ + y*WW + x;
#pragma unroll 4
    for (int c = 0; c < CC_FEAT; c++) {
        float v = ea*fp[oa] + eb*fp[ob] + ec*fp[oc] + ed*fp[od];
        *outp = v;
        fp += HWSZ; outp += HWSZ;
    }
}

// ---------------------------------------------------------------------------
// correlation + leaky relu -> split bf16 chunk16 output (fused)
// ---------------------------------------------------------------------------
__global__ void k_corr(const float* __restrict__ first) {
    const int tx = threadIdx.x, ty = threadIdx.y;
    const int x0 = blockIdx.x*32, y0 = blockIdx.y*8, b = blockIdx.z;
    __shared__ float s_f[4][8][32];
    __shared__ float s_p[4][14][40];
    float acc[49];
#pragma unroll
    for (int i = 0; i < 49; i++) acc[i] = 0.f;
    const int tid = ty*32 + tx;

    for (int c0 = 0; c0 < CC_FEAT; c0 += 4) {
#pragma unroll
        for (int cc = 0; cc < 4; cc++)
            s_f[cc][ty][tx] = first[((b*CC_FEAT + c0+cc)*HH + y0+ty)*WW + x0+tx];
        for (int i = tid; i < 4*14*38; i += 256) {
            int cc  = i / (14*38);
            int r   = (i / 38) % 14;
            int col = i % 38;
            int gy = y0 + r - 3, gx = x0 + col - 3;
            float v = 0.f;
            if (gy >= 0 && gy < HH && gx >= 0 && gx < WW)
                v = g_feat2[((b*CC_FEAT + c0+cc)*HH + gy)*WW + gx];
            s_p[cc][r][col] = v;
        }
        __syncthreads();
#pragma unroll
        for (int cc = 0; cc < 4; cc++) {
            float f = s_f[cc][ty][tx];
#pragma unroll
            for (int dy = 0; dy < 7; dy++)
#pragma unroll
                for (int dx = 0; dx < 7; dx++)
                    acc[dy*7+dx] += f * s_p[cc][ty+dy][tx+dx];
        }
        __syncthreads();
    }
    const float inv = 1.f/96.f;
    const int yy = y0 + ty, xx = x0 + tx;
#pragma unroll
    for (int chunk = 0; chunk < 4; chunk++) {
        u32 ph[8], pl[8];
#pragma unroll
        for (int kp = 0; kp < 8; kp++) {
            int d0 = chunk*16 + kp*2, d1 = d0 + 1;
            float v0 = 0.f, v1 = 0.f;
            if (d0 < 49) { v0 = acc[d0]*inv; v0 = (v0 >= 0.f) ? v0 : 0.1f*v0; }
            if (d1 < 49) { v1 = acc[d1]*inv; v1 = (v1 >= 0.f) ? v1 : 0.1f*v1; }
            unsigned short h0, l0, h1, l1;
            split_bf16(v0, h0, l0);
            split_bf16(v1, h1, l1);
            ph[kp] = ((u32)h1 << 16) | h0;
            pl[kp] = ((u32)l1 << 16) | l0;
        }
        size_t o = ((((size_t)b*4 + chunk)*HH + yy)*WW + xx)*16;
        ((uint4*)(g_a0h + o))[0] = make_uint4(ph[0], ph[1], ph[2], ph[3]);
        ((uint4*)(g_a0h + o))[1] = make_uint4(ph[4], ph[5], ph[6], ph[7]);
        ((uint4*)(g_a0l + o))[0] = make_uint4(pl[0], pl[1], pl[2], pl[3]);
        ((uint4*)(g_a0l + o))[1] = make_uint4(pl[4], pl[5], pl[6], pl[7]);
    }
}

// ---------------------------------------------------------------------------
// final 5x5 conv (32->2) + bias + flow residual
// ---------------------------------------------------------------------------
__global__ void k_conv4(const float* __restrict__ wt, const float* __restrict__ bias,
                        float* __restrict__ out) {
    const int tx = threadIdx.x, ty = threadIdx.y;
    const int x0 = blockIdx.x*32, y0 = blockIdx.y*32;
    const int b = blockIdx.z;
    __shared__ float s_in[4][36][36];
    __shared__ float s_w[2][4][25];
    float acc[4][2];
#pragma unroll
    for (int p = 0; p < 4; p++) { acc[p][0] = 0.f; acc[p][1] = 0.f; }
    const int tid = ty*32 + tx;

    for (int c0 = 0; c0 < 32; c0 += 4) {
        if (tid < 200) {
            int co = tid/100, r = tid%100, ci = r/25, k = r%25;
            s_w[co][ci][k] = wt[(co*32 + c0+ci)*25 + k];
        }
        for (int i = tid; i < 4*36*36; i += 256) {
            int cc = i/(36*36), r = (i/36)%36, col = i%36;
            int gy = y0 + r - 2, gx = x0 + col - 2;
            float v = 0.f;
            if (gy >= 0 && gy < HH && gx >= 0 && gx < WW)
                v = g_x3[((b*32 + c0+cc)*HH + gy)*WW + gx];
            s_in[cc][r][col] = v;
        }
        __syncthreads();
        for (int ci = 0; ci < 4; ci++) {
#pragma unroll
            for (int k = 0; k < 25; k++) {
                const int ky = k/5, kx = k%5;
                float w0 = s_w[0][ci][k];
                float w1 = s_w[1][ci][k];
#pragma unroll
                for (int p = 0; p < 4; p++) {
                    float iv = s_in[ci][ty + 8*p + ky][tx + kx];
                    acc[p][0] += iv * w0;
                    acc[p][1] += iv * w1;
                }
            }
        }
        __syncthreads();
    }
#pragma unroll
    for (int co = 0; co < 2; co++) {
        float bs = bias[co];
#pragma unroll
        for (int p = 0; p < 4; p++) {
            int o = ((b*2 + co)*HH + y0 + ty + 8*p)*WW + x0 + tx;
            out[o] = g_flow[o] + bs + acc[p][co];
        }
    }
}

// ---------------------------------------------------------------------------
extern "C" void kernel_launch(void* const* d_in, const int* in_sizes, int n_in,
                              void* d_out, int out_size) {
    const float* featFirst  = (const float*)d_in[2];
    const float* featSecond = (const float*)d_in[3];
    const float* tflow      = (const float*)d_in[4];
    const float* wu         = (const float*)d_in[5];
    const float* w1 = (const float*)d_in[6];
    const float* b1 = (const float*)d_in[7];
    const float* w2 = (const float*)d_in[8];
    const float* b2 = (const float*)d_in[9];
    const float* w3 = (const float*)d_in[10];
    const float* b3 = (const float*)d_in[11];
    const float* w4 = (const float*)d_in[12];
    const float* b4 = (const float*)d_in[13];
    float* out = (float*)d_out;

    const int SMB = 4*3*132*16*2*2;   // 101376 bytes
    cudaFuncSetAttribute(k_conv1m, cudaFuncAttributeMaxDynamicSharedMemorySize, SMB);
    cudaFuncSetAttribute(k_conv2m, cudaFuncAttributeMaxDynamicSharedMemorySize, SMB);
    cudaFuncSetAttribute(k_conv3m, cudaFuncAttributeMaxDynamicSharedMemorySize, SMB);

    __nv_bfloat16 *w1h, *w1l, *w2h, *w2l, *w3h, *w3l;
    cudaGetSymbolAddress((void**)&w1h, g_w1h); cudaGetSymbolAddress((void**)&w1l, g_w1l);
    cudaGetSymbolAddress((void**)&w2h, g_w2h); cudaGetSymbolAddress((void**)&w2l, g_w2l);
    cudaGetSymbolAddress((void**)&w3h, g_w3h); cudaGetSymbolAddress((void**)&w3l, g_w3l);

    // weight prep
    k_wprep<<<288, 256>>>(w1, w1h, w1l, 128, 49, 4);
    k_wprep<<<288, 256>>>(w2, w2h, w2l, 64, 128, 8);
    k_wprep<<<72,  256>>>(w3, w3h, w3l, 32, 64, 4);

    k_upflow<<<512, 1024>>>(tflow, wu);
    k_warp<<<dim3(128, 16), 128>>>(featSecond);
    k_corr<<<dim3(4, 16, 16), dim3(32, 8)>>>(featFirst);

    k_conv1m<<<dim3(128, 16), 256, SMB>>>(b1);
    k_conv2m<<<dim3(128, 16), 256, SMB>>>(b2);
    k_conv3m<<<dim3(128, 16), 256, SMB>>>(b3);
    k_conv4<<<dim3(4, 4, 16), dim3(32, 8)>>>(w4, b4, out);
}